// round 4
// baseline (speedup 1.0000x reference)
#include <cuda_runtime.h>
#include <math.h>

// Problem constants (fixed by the reference).
#define NN    10000
#define FIN   70
#define HEADS 4
#define HID   256
#define C1    (HEADS*HID)      // 1024
#define EMX   160000
#define ETMX  (EMX + NN)       // edges + self loops

// ---------------- scratch (device globals; no allocation allowed) ----------
__device__ float    g_h1  [(size_t)NN * C1];
__device__ float    g_out1[(size_t)NN * C1];
__device__ float    g_h2  [(size_t)NN * HID];
__device__ float    g_out2[(size_t)NN * HID];
__device__ float    g_as1 [NN * HEADS];
__device__ float    g_ad1 [NN * HEADS];
__device__ unsigned g_max1[NN * HEADS];
__device__ float    g_den1[NN * HEADS];
__device__ float    g_e1  [(size_t)ETMX * HEADS];
__device__ float    g_as2 [NN];
__device__ float    g_ad2 [NN];
__device__ unsigned g_max2[NN];
__device__ float    g_den2[NN];
__device__ float    g_e2  [ETMX];
__device__ float    g_pooled[HID];

// ---------------- helpers ---------------------------------------------------
// Monotone float<->uint mapping so atomicMax(unsigned) == float max.
__device__ __forceinline__ unsigned fmap(float f) {
    unsigned u = __float_as_uint(f);
    return (u >> 31) ? ~u : (u | 0x80000000u);
}
__device__ __forceinline__ float funmap(unsigned u) {
    return (u >> 31) ? __uint_as_float(u & 0x7fffffffu) : __uint_as_float(~u);
}

// Vector float4 reduction to global (sm_90+). 4x fewer RED ops than atomicAdd.
__device__ __forceinline__ void red_add_v4(float* addr, float4 v) {
    asm volatile("red.global.add.v4.f32 [%0], {%1, %2, %3, %4};"
                 :: "l"(addr), "f"(v.x), "f"(v.y), "f"(v.z), "f"(v.w)
                 : "memory");
}

__device__ __forceinline__ void edge_sd(const int* ei, int E, int e, int& s, int& d) {
    if (e < E) { s = ei[e]; d = ei[E + e]; }
    else       { s = d = e - E; }           // self loop
}

// ---------------- generic fp32 GEMM: C[M,N] = A[M,K] @ B[K,N] ----------------
// 128x128x16 tile, 256 threads, 8x8 microtile. Requires N % 128 == 0.
#define BM 128
#define BN 128
#define BK 16
#define TM 8
#define TN 8

__global__ __launch_bounds__(256) void gemm_f32(
    const float* __restrict__ A, const float* __restrict__ B,
    float* __restrict__ C, int M, int N, int K)
{
    __shared__ float As[BK][BM + 4];
    __shared__ float Bs[BK][BN];

    const int tid = threadIdx.x;
    const int tx = tid & 15;         // 0..15 -> N
    const int ty = tid >> 4;         // 0..15 -> M
    const int bm = blockIdx.y * BM;
    const int bn = blockIdx.x * BN;
    const int row0 = bm + ty * TM;
    const int col0 = bn + tx * TN;

    float acc[TM][TN];
#pragma unroll
    for (int i = 0; i < TM; i++)
#pragma unroll
        for (int j = 0; j < TN; j++) acc[i][j] = 0.f;

    for (int k0 = 0; k0 < K; k0 += BK) {
        // A tile (transposed into smem)
#pragma unroll
        for (int it = 0; it < (BM * BK) / 256; it++) {
            int idx = tid + it * 256;
            int m = idx >> 4, k = idx & 15;
            int gm = bm + m, gk = k0 + k;
            As[k][m] = (gm < M && gk < K) ? A[(size_t)gm * K + gk] : 0.f;
        }
        // B tile (row-major, float4)
#pragma unroll
        for (int it = 0; it < (BK * BN) / 1024; it++) {
            int f4 = tid + it * 256;                // 0..511
            int k = f4 >> 5, c = (f4 & 31) << 2;
            int gk = k0 + k;
            float4 v = make_float4(0.f, 0.f, 0.f, 0.f);
            if (gk < K) v = *(const float4*)&B[(size_t)gk * N + bn + c];
            *(float4*)&Bs[k][c] = v;
        }
        __syncthreads();

#pragma unroll
        for (int kk = 0; kk < BK; kk++) {
            float a[TM], b[TN];
            *(float4*)&a[0] = *(float4*)&As[kk][ty * TM];
            *(float4*)&a[4] = *(float4*)&As[kk][ty * TM + 4];
            *(float4*)&b[0] = *(float4*)&Bs[kk][tx * TN];
            *(float4*)&b[4] = *(float4*)&Bs[kk][tx * TN + 4];
#pragma unroll
            for (int i = 0; i < TM; i++)
#pragma unroll
                for (int j = 0; j < TN; j++)
                    acc[i][j] = fmaf(a[i], b[j], acc[i][j]);
        }
        __syncthreads();
    }

#pragma unroll
    for (int i = 0; i < TM; i++) {
        int r = row0 + i;
        if (r < M) {
#pragma unroll
            for (int j = 0; j < TN; j += 4) {
                float4 v = make_float4(acc[i][j], acc[i][j+1], acc[i][j+2], acc[i][j+3]);
                *(float4*)&C[(size_t)r * N + col0 + j] = v;
            }
        }
    }
}

// ---------------- layer 1 ----------------------------------------------------
// per (node, head) dot with att_src1/att_dst1 (one warp each)
__global__ void att1_kernel(const float* __restrict__ asrc,
                            const float* __restrict__ adst, int n)
{
    int wid = (blockIdx.x * blockDim.x + threadIdx.x) >> 5;
    int lane = threadIdx.x & 31;
    if (wid >= n * HEADS) return;
    int node = wid >> 2, h = wid & 3;
    const float* x = g_h1 + (size_t)node * C1 + h * HID;
    const float* s = asrc + h * HID;
    const float* d = adst + h * HID;
    float ss = 0.f, dd = 0.f;
#pragma unroll
    for (int i = lane; i < HID; i += 32) {
        float v = x[i];
        ss = fmaf(v, s[i], ss);
        dd = fmaf(v, d[i], dd);
    }
#pragma unroll
    for (int o = 16; o; o >>= 1) {
        ss += __shfl_down_sync(0xffffffffu, ss, o);
        dd += __shfl_down_sync(0xffffffffu, dd, o);
    }
    if (lane == 0) { g_as1[node * HEADS + h] = ss; g_ad1[node * HEADS + h] = dd; }
}

__global__ void init1_kernel(const float* __restrict__ b1, int n) {
    int i = blockIdx.x * blockDim.x + threadIdx.x;
    if (i < n * C1) g_out1[i] = b1[i & (C1 - 1)];   // bias-initialized accumulator
    if (i < n * HEADS) { g_max1[i] = 0u; g_den1[i] = 0.f; }
}

__global__ void edge_score1(const int* __restrict__ ei, int E, int n) {
    int e = blockIdx.x * blockDim.x + threadIdx.x;
    if (e >= E + n) return;
    int s, d; edge_sd(ei, E, e, s, d);
    float4 a = *(const float4*)&g_as1[s * HEADS];
    float4 b = *(const float4*)&g_ad1[d * HEADS];
    float v[4] = {a.x + b.x, a.y + b.y, a.z + b.z, a.w + b.w};
#pragma unroll
    for (int h = 0; h < 4; h++) {
        v[h] = v[h] > 0.f ? v[h] : 0.2f * v[h];
        atomicMax(&g_max1[d * HEADS + h], fmap(v[h]));
    }
    *(float4*)&g_e1[(size_t)e * HEADS] = make_float4(v[0], v[1], v[2], v[3]);
}

__global__ void edge_exp1(const int* __restrict__ ei, int E, int n) {
    int e = blockIdx.x * blockDim.x + threadIdx.x;
    if (e >= E + n) return;
    int s, d; edge_sd(ei, E, e, s, d);
    float4 v = *(const float4*)&g_e1[(size_t)e * HEADS];
    float ex[4];
    ex[0] = expf(v.x - funmap(g_max1[d * HEADS + 0]));
    ex[1] = expf(v.y - funmap(g_max1[d * HEADS + 1]));
    ex[2] = expf(v.z - funmap(g_max1[d * HEADS + 2]));
    ex[3] = expf(v.w - funmap(g_max1[d * HEADS + 3]));
#pragma unroll
    for (int h = 0; h < 4; h++) atomicAdd(&g_den1[d * HEADS + h], ex[h]);
    *(float4*)&g_e1[(size_t)e * HEADS] = make_float4(ex[0], ex[1], ex[2], ex[3]);
}

// one block (256 thr) per edge: 1024 channels as 256 float4 RED ops
__global__ __launch_bounds__(256) void aggregate1(const int* __restrict__ ei, int E, int n) {
    int e = blockIdx.x;
    int s, d; edge_sd(ei, E, e, s, d);
    __shared__ float alpha[HEADS];
    int t = threadIdx.x;
    if (t < HEADS) alpha[t] = g_e1[(size_t)e * HEADS + t] / (g_den1[d * HEADS + t] + 1e-16f);
    __syncthreads();
    int h = t >> 6;                 // 0..3
    int c = (t & 63) << 2;          // 0..252
    float a = alpha[h];
    float4 v = *(const float4*)&g_h1[(size_t)s * C1 + h * HID + c];
    red_add_v4(&g_out1[(size_t)d * C1 + h * HID + c],
               make_float4(v.x * a, v.y * a, v.z * a, v.w * a));
}

__global__ void relu1_kernel(int n) {
    int i = blockIdx.x * blockDim.x + threadIdx.x;
    if (i < n * C1) g_out1[i] = fmaxf(g_out1[i], 0.f);
}

// ---------------- layer 2 ----------------------------------------------------
__global__ void att2_kernel(const float* __restrict__ asrc,
                            const float* __restrict__ adst, int n)
{
    int wid = (blockIdx.x * blockDim.x + threadIdx.x) >> 5;
    int lane = threadIdx.x & 31;
    if (wid >= n) return;
    const float* x = g_h2 + (size_t)wid * HID;
    float ss = 0.f, dd = 0.f;
#pragma unroll
    for (int i = lane; i < HID; i += 32) {
        float v = x[i];
        ss = fmaf(v, asrc[i], ss);
        dd = fmaf(v, adst[i], dd);
    }
#pragma unroll
    for (int o = 16; o; o >>= 1) {
        ss += __shfl_down_sync(0xffffffffu, ss, o);
        dd += __shfl_down_sync(0xffffffffu, dd, o);
    }
    if (lane == 0) { g_as2[wid] = ss; g_ad2[wid] = dd; }
}

__global__ void init2_kernel(const float* __restrict__ b2, int n) {
    int i = blockIdx.x * blockDim.x + threadIdx.x;
    if (i < n * HID) g_out2[i] = b2[i & (HID - 1)];
    if (i < n) { g_max2[i] = 0u; g_den2[i] = 0.f; }
    if (i < HID) g_pooled[i] = 0.f;
}

__global__ void edge_score2(const int* __restrict__ ei, int E, int n) {
    int e = blockIdx.x * blockDim.x + threadIdx.x;
    if (e >= E + n) return;
    int s, d; edge_sd(ei, E, e, s, d);
    float v = g_as2[s] + g_ad2[d];
    v = v > 0.f ? v : 0.2f * v;
    g_e2[e] = v;
    atomicMax(&g_max2[d], fmap(v));
}

__global__ void edge_exp2(const int* __restrict__ ei, int E, int n) {
    int e = blockIdx.x * blockDim.x + threadIdx.x;
    if (e >= E + n) return;
    int s, d; edge_sd(ei, E, e, s, d);
    float ex = expf(g_e2[e] - funmap(g_max2[d]));
    g_e2[e] = ex;
    atomicAdd(&g_den2[d], ex);
}

// 4 edges per 256-thread block; 64 lanes (= 64 float4) per edge
__global__ __launch_bounds__(256) void aggregate2(const int* __restrict__ ei, int E, int n) {
    int sub = threadIdx.x >> 6;
    int lane = threadIdx.x & 63;
    int e = blockIdx.x * 4 + sub;
    if (e >= E + n) return;
    int s, d; edge_sd(ei, E, e, s, d);
    float a = g_e2[e] / (g_den2[d] + 1e-16f);
    int c = lane << 2;
    float4 v = *(const float4*)&g_h2[(size_t)s * HID + c];
    red_add_v4(&g_out2[(size_t)d * HID + c],
               make_float4(v.x * a, v.y * a, v.z * a, v.w * a));
}

// relu + column-sum pooling
__global__ void pool_kernel(int n) {
    int c = threadIdx.x;        // 256
    float acc = 0.f;
    for (int r = blockIdx.x; r < n; r += gridDim.x)
        acc += fmaxf(g_out2[(size_t)r * HID + c], 0.f);
    atomicAdd(&g_pooled[c], acc);
}

// mean -> Linear(256,128) -> exact GELU -> Linear(128,1)
__global__ void final_kernel(const float* __restrict__ Wv1, const float* __restrict__ bv1,
                             const float* __restrict__ Wv2, const float* __restrict__ bv2,
                             float* __restrict__ out, int n)
{
    __shared__ float p[HID];
    __shared__ float red[128];
    int t = threadIdx.x;        // 128
    float inv = 1.f / (float)n;
    p[t]       = g_pooled[t] * inv;
    p[t + 128] = g_pooled[t + 128] * inv;
    __syncthreads();
    float acc = bv1[t];
#pragma unroll 8
    for (int k = 0; k < HID; k++) acc = fmaf(p[k], Wv1[k * 128 + t], acc);
    float g = 0.5f * acc * (1.f + erff(acc * 0.70710678118654752f));
    red[t] = g * Wv2[t];
    __syncthreads();
#pragma unroll
    for (int o = 64; o; o >>= 1) {
        if (t < o) red[t] += red[t + o];
        __syncthreads();
    }
    if (t == 0) out[0] = red[0] + bv2[0];
}

// ---------------- launcher ---------------------------------------------------
extern "C" void kernel_launch(void* const* d_in, const int* in_sizes, int n_in,
                              void* d_out, int out_size)
{
    const float* X   = (const float*)d_in[0];
    const int*   EI  = (const int*)  d_in[1];
    // d_in[2] edge_attr: ignored (GATConv has no edge_dim)
    const float* W1  = (const float*)d_in[3];
    const float* as1 = (const float*)d_in[4];
    const float* ad1 = (const float*)d_in[5];
    const float* b1  = (const float*)d_in[6];
    const float* W2  = (const float*)d_in[7];
    const float* as2 = (const float*)d_in[8];
    const float* ad2 = (const float*)d_in[9];
    const float* b2  = (const float*)d_in[10];
    const float* Wv1 = (const float*)d_in[11];
    const float* bv1 = (const float*)d_in[12];
    const float* Wv2 = (const float*)d_in[13];
    const float* bv2 = (const float*)d_in[14];
    float* out = (float*)d_out;

    int n = in_sizes[0] / FIN;       // 10000
    int E = in_sizes[1] / 2;         // 160000
    int etot = E + n;

    float *p_h1, *p_out1, *p_h2;
    cudaGetSymbolAddress((void**)&p_h1,   g_h1);
    cudaGetSymbolAddress((void**)&p_out1, g_out1);
    cudaGetSymbolAddress((void**)&p_h2,   g_h2);

    // ---- layer 1 ----
    {
        dim3 grid(C1 / BN, (n + BM - 1) / BM);
        gemm_f32<<<grid, 256>>>(X, W1, p_h1, n, C1, FIN);
    }
    att1_kernel<<<(n * HEADS * 32 + 255) / 256, 256>>>(as1, ad1, n);
    init1_kernel<<<(n * C1 + 255) / 256, 256>>>(b1, n);
    edge_score1<<<(etot + 255) / 256, 256>>>(EI, E, n);
    edge_exp1  <<<(etot + 255) / 256, 256>>>(EI, E, n);
    aggregate1 <<<etot, 256>>>(EI, E, n);
    relu1_kernel<<<(n * C1 + 255) / 256, 256>>>(n);

    // ---- layer 2 ----
    {
        dim3 grid(HID / BN, (n + BM - 1) / BM);
        gemm_f32<<<grid, 256>>>(p_out1, W2, p_h2, n, HID, C1);
    }
    att2_kernel<<<(n * 32 + 255) / 256, 256>>>(as2, ad2, n);
    init2_kernel<<<(n * HID + 255) / 256, 256>>>(b2, n);
    edge_score2<<<(etot + 255) / 256, 256>>>(EI, E, n);
    edge_exp2  <<<(etot + 255) / 256, 256>>>(EI, E, n);
    aggregate2 <<<(etot + 3) / 4, 256>>>(EI, E, n);

    // ---- head ----
    pool_kernel<<<128, 256>>>(n);
    final_kernel<<<1, 128>>>(Wv1, bv1, Wv2, bv2, out, n);
}